// round 2
// baseline (speedup 1.0000x reference)
#include <cuda_runtime.h>
#include <math.h>

#define H  1024
#define V  50257
#define L  512
#define H4 (H / 4)        // 256 float4 per H row
#define H2_4 (2 * H / 4)  // 512 float4 per 2H row

// ---------------- scratch (device globals; no allocations) ----------------
__device__ float    g_scores[L];
__device__ float    g_weights[L];
__device__ float    g_attn[H];
__device__ float    g_x[H];
__device__ float    g_gh[3 * H];
__device__ float    g_hnew[H];
__device__ float    g_logits[V];
__device__ unsigned g_max_u;        // order-encoded float max
__device__ float    g_partial[256]; // blockwise sum-exp partials
__device__ float    g_logZ;

// ---------------- helpers ----------------
__device__ __forceinline__ float warp_reduce(float v) {
#pragma unroll
    for (int o = 16; o; o >>= 1) v += __shfl_xor_sync(0xffffffffu, v, o);
    return v;
}

// order-preserving float<->unsigned encoding for atomicMax
__device__ __forceinline__ unsigned f2u_ord(float f) {
    int i = __float_as_int(f);
    return (i >= 0) ? ((unsigned)i | 0x80000000u) : ~((unsigned)i);
}
__device__ __forceinline__ float u2f_ord(unsigned u) {
    int i = (u & 0x80000000u) ? (int)(u & 0x7fffffffu) : ~(int)u;
    return __int_as_float(i);
}

__device__ __forceinline__ float dot4(float4 a, float4 b) {
    return a.x * b.x + a.y * b.y + a.z * b.z + a.w * b.w;
}

// ---------------- K1: attention scores  a[l] = [emb, h0] . attn_W[l] + b ----
// 128 blocks x 128 threads = 512 warps, one warp per score
__global__ void k_scores(const int* __restrict__ ids,
                         const float* __restrict__ hidden,
                         const float* __restrict__ emb,
                         const float* __restrict__ attn_W,
                         const float* __restrict__ attn_b) {
    int warp = threadIdx.x >> 5, lane = threadIdx.x & 31;
    int l = blockIdx.x * 4 + warp;
    const float4* row = (const float4*)(attn_W + (size_t)l * 2 * H);
    const float4* e4  = (const float4*)(emb + (size_t)ids[0] * H);
    const float4* h4  = (const float4*)hidden;
    float acc = 0.f;
#pragma unroll 4
    for (int j = lane; j < H2_4; j += 32) {
        float4 a = row[j];
        float4 b = (j < H4) ? e4[j] : h4[j - H4];
        acc += dot4(a, b);
    }
    acc = warp_reduce(acc);
    if (!lane) g_scores[l] = acc + attn_b[l];
}

// ---------------- K2: softmax over L (one block), write attn_weights out ---
__global__ void k_softmax(float* __restrict__ out) {
    __shared__ float sh[L];
    int t = threadIdx.x;
    float s = g_scores[t];
    sh[t] = s;
    __syncthreads();
    for (int o = L / 2; o; o >>= 1) {
        if (t < o) sh[t] = fmaxf(sh[t], sh[t + o]);
        __syncthreads();
    }
    float m = sh[0];
    __syncthreads();
    float e = expf(s - m);
    sh[t] = e;
    __syncthreads();
    for (int o = L / 2; o; o >>= 1) {
        if (t < o) sh[t] += sh[t + o];
        __syncthreads();
    }
    float w = e / sh[0];
    g_weights[t] = w;
    out[V + H + t] = w;
    if (!t) g_max_u = 0u;  // reset vocab-max accumulator for this replay
}

// ---------------- K3: attn_applied[h] = sum_l w[l] * enc[l][h] -------------
// 8 blocks x (128 x 8) threads: x = h within block, y = l-chunk
__global__ void k_attn(const float* __restrict__ enc) {
    __shared__ float sh[8][128];
    int h = blockIdx.x * 128 + threadIdx.x;
    int yc = threadIdx.y;
    float acc = 0.f;
    int l0 = yc * (L / 8);
#pragma unroll 4
    for (int l = l0; l < l0 + L / 8; l++)
        acc += g_weights[l] * enc[(size_t)l * H + h];
    sh[yc][threadIdx.x] = acc;
    __syncthreads();
    if (yc == 0) {
        float s = 0.f;
#pragma unroll
        for (int k = 0; k < 8; k++) s += sh[k][threadIdx.x];
        g_attn[h] = s;
    }
}

// ---------------- K4: x = relu(comb_W.[emb,attn]+b)  AND  gh = W_hh.h0+b ---
// 512 blocks x 256 threads (8 warps) -> 4096 warps: first 1024 -> x, rest -> gh
__global__ void k_x_gh(const int* __restrict__ ids,
                       const float* __restrict__ hidden,
                       const float* __restrict__ emb,
                       const float* __restrict__ comb_W,
                       const float* __restrict__ comb_b,
                       const float* __restrict__ W_hh,
                       const float* __restrict__ b_hh) {
    int warp = threadIdx.x >> 5, lane = threadIdx.x & 31;
    int g = blockIdx.x * 8 + warp;
    if (g < H) {
        const float4* row = (const float4*)(comb_W + (size_t)g * 2 * H);
        const float4* e4  = (const float4*)(emb + (size_t)ids[0] * H);
        const float4* a4  = (const float4*)g_attn;
        float acc = 0.f;
#pragma unroll 4
        for (int j = lane; j < H2_4; j += 32) {
            float4 a = row[j];
            float4 b = (j < H4) ? e4[j] : a4[j - H4];
            acc += dot4(a, b);
        }
        acc = warp_reduce(acc);
        if (!lane) g_x[g] = fmaxf(acc + comb_b[g], 0.f);
    } else {
        int r = g - H;  // 0..3071
        const float4* row = (const float4*)(W_hh + (size_t)r * H);
        const float4* h4  = (const float4*)hidden;
        float acc = 0.f;
#pragma unroll 4
        for (int j = lane; j < H4; j += 32) acc += dot4(row[j], h4[j]);
        acc = warp_reduce(acc);
        if (!lane) g_gh[r] = acc + b_hh[r];
    }
}

// ---------------- K5: gi = W_ih.x + b ; GRU gates -> h_new ----------------
// 128 blocks x 256 threads: warp i computes rows i, H+i, 2H+i then gate math
__global__ void k_gates(const float* __restrict__ hidden,
                        const float* __restrict__ W_ih,
                        const float* __restrict__ b_ih,
                        float* __restrict__ out) {
    int warp = threadIdx.x >> 5, lane = threadIdx.x & 31;
    int i = blockIdx.x * 8 + warp;  // 0..1023
    const float4* x4 = (const float4*)g_x;
    const float4* r0 = (const float4*)(W_ih + (size_t)i * H);
    const float4* r1 = (const float4*)(W_ih + (size_t)(H + i) * H);
    const float4* r2 = (const float4*)(W_ih + (size_t)(2 * H + i) * H);
    float a0 = 0.f, a1 = 0.f, a2 = 0.f;
#pragma unroll 4
    for (int j = lane; j < H4; j += 32) {
        float4 b = x4[j];
        a0 += dot4(r0[j], b);
        a1 += dot4(r1[j], b);
        a2 += dot4(r2[j], b);
    }
    a0 = warp_reduce(a0);
    a1 = warp_reduce(a1);
    a2 = warp_reduce(a2);
    if (!lane) {
        float ir = a0 + b_ih[i];
        float iz = a1 + b_ih[H + i];
        float in_ = a2 + b_ih[2 * H + i];
        float hr = g_gh[i], hz = g_gh[H + i], hn = g_gh[2 * H + i];
        float r = 1.f / (1.f + expf(-(ir + hr)));
        float z = 1.f / (1.f + expf(-(iz + hz)));
        float n = tanhf(in_ + r * hn);
        float h0 = hidden[i];
        float hnew = (1.f - z) * n + z * h0;
        g_hnew[i] = hnew;
        out[V + i] = hnew;
    }
}

// ---------------- K6: vocab GEMV + per-block max ---------------------------
// warp per row; 8 rows/block; grid = ceil(V/8)
__global__ void k_logits(const float* __restrict__ out_W,
                         const float* __restrict__ out_b) {
    __shared__ float smax[8];
    int warp = threadIdx.x >> 5, lane = threadIdx.x & 31;
    int r = blockIdx.x * 8 + warp;
    float logit = -INFINITY;
    if (r < V) {
        const float4* row = (const float4*)(out_W + (size_t)r * H);
        const float4* h4  = (const float4*)g_hnew;
        float acc = 0.f;
#pragma unroll
        for (int j = lane; j < H4; j += 32) acc += dot4(row[j], h4[j]);
        acc = warp_reduce(acc);
        logit = acc + out_b[r];
        if (!lane) g_logits[r] = logit;
    }
    if (!lane) smax[warp] = logit;
    __syncthreads();
    if (threadIdx.x == 0) {
        float m = smax[0];
#pragma unroll
        for (int k = 1; k < 8; k++) m = fmaxf(m, smax[k]);
        atomicMax(&g_max_u, f2u_ord(m));  // order-invariant -> deterministic
    }
}

// ---------------- K7: blockwise sum of exp(logit - max) --------------------
#define SE_BLOCKS ((V + 255) / 256)  // 197
__global__ void k_sumexp() {
    __shared__ float sh[256];
    int i = blockIdx.x * 256 + threadIdx.x;
    float m = u2f_ord(g_max_u);
    float e = (i < V) ? expf(g_logits[i] - m) : 0.f;
    sh[threadIdx.x] = e;
    __syncthreads();
    for (int o = 128; o; o >>= 1) {
        if (threadIdx.x < o) sh[threadIdx.x] += sh[threadIdx.x + o];
        __syncthreads();
    }
    if (!threadIdx.x) g_partial[blockIdx.x] = sh[0];
}

// ---------------- K8: reduce partials -> logZ ------------------------------
__global__ void k_logz() {
    __shared__ float sh[256];
    int t = threadIdx.x;
    sh[t] = (t < SE_BLOCKS) ? g_partial[t] : 0.f;
    __syncthreads();
    for (int o = 128; o; o >>= 1) {
        if (t < o) sh[t] += sh[t + o];
        __syncthreads();
    }
    if (!t) g_logZ = u2f_ord(g_max_u) + logf(sh[0]);
}

// ---------------- K9: write log-softmax ------------------------------------
__global__ void k_write(float* __restrict__ out) {
    int i = blockIdx.x * 256 + threadIdx.x;
    if (i < V) out[i] = g_logits[i] - g_logZ;
}

// ---------------- launch ----------------------------------------------------
extern "C" void kernel_launch(void* const* d_in, const int* in_sizes, int n_in,
                              void* d_out, int out_size) {
    const int*   ids    = (const int*)d_in[0];
    const float* hidden = (const float*)d_in[1];
    const float* enc    = (const float*)d_in[2];
    const float* emb    = (const float*)d_in[3];
    const float* attn_W = (const float*)d_in[4];
    const float* attn_b = (const float*)d_in[5];
    const float* comb_W = (const float*)d_in[6];
    const float* comb_b = (const float*)d_in[7];
    const float* W_ih   = (const float*)d_in[8];
    const float* W_hh   = (const float*)d_in[9];
    const float* b_ih   = (const float*)d_in[10];
    const float* b_hh   = (const float*)d_in[11];
    const float* out_W  = (const float*)d_in[12];
    const float* out_b  = (const float*)d_in[13];
    float* out = (float*)d_out;

    k_scores<<<L / 4, 128>>>(ids, hidden, emb, attn_W, attn_b);
    k_softmax<<<1, L>>>(out);
    {
        dim3 blk(128, 8);
        k_attn<<<H / 128, blk>>>(enc);
    }
    k_x_gh<<<(H + 3 * H) / 8, 256>>>(ids, hidden, emb, comb_W, comb_b, W_hh, b_hh);
    k_gates<<<H / 8, 256>>>(hidden, W_ih, b_ih, out);
    k_logits<<<(V + 7) / 8, 256>>>(out_W, out_b);
    k_sumexp<<<SE_BLOCKS, 256>>>();
    k_logz<<<1, 256>>>();
    k_write<<<(V + 255) / 256, 256>>>(out);
}

// round 3
// speedup vs baseline: 1.2332x; 1.2332x over previous
#include <cuda_runtime.h>
#include <math.h>

#define H  1024
#define V  50257
#define L  512
#define H4 (H / 4)        // 256 float4 per H-length row

// ---------------- scratch (device globals; no allocations) ----------------
__device__ float    g_scores[L];
__device__ float    g_weights[L];
__device__ float    g_attn_part[4][H];
__device__ float    g_x[H];
__device__ float    g_gh[3 * H];
__device__ float    g_hnew[H];
__device__ float    g_logits[V];
__device__ unsigned g_max_u;        // order-encoded float max
__device__ float    g_partial[256]; // blockwise sum-exp partials

// ---------------- helpers ----------------
__device__ __forceinline__ float warp_reduce(float v) {
#pragma unroll
    for (int o = 16; o; o >>= 1) v += __shfl_xor_sync(0xffffffffu, v, o);
    return v;
}
__device__ __forceinline__ unsigned f2u_ord(float f) {
    int i = __float_as_int(f);
    return (i >= 0) ? ((unsigned)i | 0x80000000u) : ~((unsigned)i);
}
__device__ __forceinline__ float u2f_ord(unsigned u) {
    int i = (u & 0x80000000u) ? (int)(u & 0x7fffffffu) : ~(int)u;
    return __int_as_float(i);
}
__device__ __forceinline__ float dot4(float4 a, float4 b) {
    return a.x * b.x + a.y * b.y + a.z * b.z + a.w * b.w;
}
__device__ __forceinline__ float4 ldcs4(const float4* p) { return __ldcs(p); }

// ==== K1: fused  scores[l] = [emb,h0].attn_W[l]+b   AND   gh = W_hh.h0+b ====
// blocks 0..127  : scores, 4 rows/block, 2 warps per 2048-row (halves)
// blocks 128..511: gh, 8 rows/block, warp per 1024-row
__global__ void __launch_bounds__(256)
k1_scores_gh(const int* __restrict__ ids,
             const float* __restrict__ hidden,
             const float* __restrict__ emb,
             const float* __restrict__ attn_W,
             const float* __restrict__ attn_b,
             const float* __restrict__ W_hh,
             const float* __restrict__ b_hh) {
    int warp = threadIdx.x >> 5, lane = threadIdx.x & 31;
    if (blockIdx.x < 128) {
        __shared__ float s_part[8];
        int row  = blockIdx.x * 4 + (warp >> 1);
        int half = warp & 1;
        const float4* row4 = (const float4*)(attn_W + (size_t)row * 2 * H) + half * H4;
        const float4* b4   = half ? (const float4*)hidden
                                  : (const float4*)(emb + (size_t)ids[0] * H);
        float acc = 0.f;
#pragma unroll
        for (int k = 0; k < 8; k++) {
            int j = lane + 32 * k;
            acc += dot4(ldcs4(row4 + j), __ldg(b4 + j));
        }
        acc = warp_reduce(acc);
        if (!lane) s_part[warp] = acc;
        __syncthreads();
        if (threadIdx.x < 4) {
            int r = blockIdx.x * 4 + threadIdx.x;
            g_scores[r] = s_part[2 * threadIdx.x] + s_part[2 * threadIdx.x + 1] + attn_b[r];
        }
    } else {
        int r = (blockIdx.x - 128) * 8 + warp;          // 0..3071
        const float4* row4 = (const float4*)(W_hh + (size_t)r * H);
        const float4* h4   = (const float4*)hidden;
        float acc = 0.f;
#pragma unroll
        for (int k = 0; k < 8; k++) {
            int j = lane + 32 * k;
            acc += dot4(ldcs4(row4 + j), __ldg(h4 + j));
        }
        acc = warp_reduce(acc);
        if (!lane) g_gh[r] = acc + b_hh[r];
    }
}

// ==== K2: softmax over L (one block), writes attn_weights output ===========
__global__ void k2_softmax(float* __restrict__ out) {
    __shared__ float sh[L];
    int t = threadIdx.x;
    float s = g_scores[t];
    sh[t] = s;
    __syncthreads();
    for (int o = L / 2; o; o >>= 1) {
        if (t < o) sh[t] = fmaxf(sh[t], sh[t + o]);
        __syncthreads();
    }
    float m = sh[0];
    __syncthreads();
    float e = expf(s - m);
    sh[t] = e;
    __syncthreads();
    for (int o = L / 2; o; o >>= 1) {
        if (t < o) sh[t] += sh[t + o];
        __syncthreads();
    }
    float w = e / sh[0];
    g_weights[t] = w;
    out[V + H + t] = w;
    if (!t) g_max_u = 0u;   // reset vocab-max accumulator for this replay
}

// ==== K3: attention-apply partials  part[y][h] = sum_{l in chunk} w*enc =====
// grid (8,4) block (128,8): 32 blocks, each thread 16 coalesced loads
__global__ void __launch_bounds__(1024)
k3_attn(const float* __restrict__ enc) {
    __shared__ float sh[8][128];
    int col = blockIdx.x * 128 + threadIdx.x;
    int r0  = blockIdx.y * 128 + threadIdx.y * 16;
    float acc = 0.f;
#pragma unroll
    for (int r = 0; r < 16; r++)
        acc += g_weights[r0 + r] * __ldcs(enc + (size_t)(r0 + r) * H + col);
    sh[threadIdx.y][threadIdx.x] = acc;
    __syncthreads();
    if (threadIdx.y == 0) {
        float s = 0.f;
#pragma unroll
        for (int k = 0; k < 8; k++) s += sh[k][threadIdx.x];
        g_attn_part[blockIdx.y][col] = s;
    }
}

// ==== K4: x = relu(comb_W.[emb, attn] + b)  — 2 warps per 2048-row =========
__global__ void __launch_bounds__(256)
k4_x(const int* __restrict__ ids,
     const float* __restrict__ emb,
     const float* __restrict__ comb_W,
     const float* __restrict__ comb_b) {
    __shared__ float s_part[8];
    int warp = threadIdx.x >> 5, lane = threadIdx.x & 31;
    int row  = blockIdx.x * 4 + (warp >> 1);
    int half = warp & 1;
    const float4* row4 = (const float4*)(comb_W + (size_t)row * 2 * H) + half * H4;
    float acc = 0.f;
    if (half == 0) {
        const float4* e4 = (const float4*)(emb + (size_t)ids[0] * H);
#pragma unroll
        for (int k = 0; k < 8; k++) {
            int j = lane + 32 * k;
            acc += dot4(ldcs4(row4 + j), __ldg(e4 + j));
        }
    } else {
        const float4* p0 = (const float4*)g_attn_part[0];
        const float4* p1 = (const float4*)g_attn_part[1];
        const float4* p2 = (const float4*)g_attn_part[2];
        const float4* p3 = (const float4*)g_attn_part[3];
#pragma unroll
        for (int k = 0; k < 8; k++) {
            int j = lane + 32 * k;
            float4 a0 = __ldg(p0 + j), a1 = __ldg(p1 + j);
            float4 a2 = __ldg(p2 + j), a3 = __ldg(p3 + j);
            float4 b;
            b.x = a0.x + a1.x + a2.x + a3.x;
            b.y = a0.y + a1.y + a2.y + a3.y;
            b.z = a0.z + a1.z + a2.z + a3.z;
            b.w = a0.w + a1.w + a2.w + a3.w;
            acc += dot4(ldcs4(row4 + j), b);
        }
    }
    acc = warp_reduce(acc);
    if (!lane) s_part[warp] = acc;
    __syncthreads();
    if (threadIdx.x < 4) {
        int r = blockIdx.x * 4 + threadIdx.x;
        g_x[r] = fmaxf(s_part[2 * threadIdx.x] + s_part[2 * threadIdx.x + 1] + comb_b[r], 0.f);
    }
}

// ==== K5: gi = W_ih.x + b ; GRU gate math -> h_new ==========================
// 256 blocks; 8 warps = 4 gate-triples x 2 half-rows; MLP=16 per warp
__global__ void __launch_bounds__(256)
k5_gates(const float* __restrict__ hidden,
         const float* __restrict__ W_ih,
         const float* __restrict__ b_ih,
         float* __restrict__ out) {
    __shared__ float s_part[8][3];
    int warp = threadIdx.x >> 5, lane = threadIdx.x & 31;
    int i    = blockIdx.x * 4 + (warp >> 1);   // 0..1023
    int half = warp & 1;
    const float4* x4 = (const float4*)g_x + half * (H4 / 2);
    const float4* r0 = (const float4*)(W_ih + (size_t)i * H)           + half * (H4 / 2);
    const float4* r1 = (const float4*)(W_ih + (size_t)(H + i) * H)     + half * (H4 / 2);
    const float4* r2 = (const float4*)(W_ih + (size_t)(2 * H + i) * H) + half * (H4 / 2);
    float a0 = 0.f, a1 = 0.f, a2 = 0.f;
#pragma unroll
    for (int k = 0; k < 4; k++) {
        int j = lane + 32 * k;
        float4 b = __ldg(x4 + j);
        a0 += dot4(ldcs4(r0 + j), b);
        a1 += dot4(ldcs4(r1 + j), b);
        a2 += dot4(ldcs4(r2 + j), b);
    }
    a0 = warp_reduce(a0);
    a1 = warp_reduce(a1);
    a2 = warp_reduce(a2);
    if (!lane) { s_part[warp][0] = a0; s_part[warp][1] = a1; s_part[warp][2] = a2; }
    __syncthreads();
    if (threadIdx.x < 4) {
        int t = threadIdx.x;
        int gi_i = blockIdx.x * 4 + t;
        float ir  = s_part[2 * t][0] + s_part[2 * t + 1][0] + b_ih[gi_i];
        float iz  = s_part[2 * t][1] + s_part[2 * t + 1][1] + b_ih[H + gi_i];
        float in_ = s_part[2 * t][2] + s_part[2 * t + 1][2] + b_ih[2 * H + gi_i];
        float hr = g_gh[gi_i], hz = g_gh[H + gi_i], hn = g_gh[2 * H + gi_i];
        float r = 1.f / (1.f + expf(-(ir + hr)));
        float z = 1.f / (1.f + expf(-(iz + hz)));
        float n = tanhf(in_ + r * hn);
        float h0 = hidden[gi_i];
        float hnew = (1.f - z) * n + z * h0;
        g_hnew[gi_i] = hnew;
        out[V + gi_i] = hnew;
    }
}

// ==== K6: vocab GEMV + deterministic global max =============================
__global__ void __launch_bounds__(256)
k6_logits(const float* __restrict__ out_W,
          const float* __restrict__ out_b) {
    __shared__ float smax[8];
    int warp = threadIdx.x >> 5, lane = threadIdx.x & 31;
    int r = blockIdx.x * 8 + warp;
    float logit = -INFINITY;
    if (r < V) {
        const float4* row4 = (const float4*)(out_W + (size_t)r * H);
        const float4* h4   = (const float4*)g_hnew;
        float acc = 0.f;
#pragma unroll
        for (int k = 0; k < 8; k++) {
            int j = lane + 32 * k;
            acc += dot4(ldcs4(row4 + j), __ldg(h4 + j));
        }
        acc = warp_reduce(acc);
        logit = acc + out_b[r];
        if (!lane) g_logits[r] = logit;
    }
    if (!lane) smax[warp] = logit;
    __syncthreads();
    if (threadIdx.x == 0) {
        float m = smax[0];
#pragma unroll
        for (int k = 1; k < 8; k++) m = fmaxf(m, smax[k]);
        atomicMax(&g_max_u, f2u_ord(m));   // order-invariant -> deterministic
    }
}

// ==== K7: blockwise sum of exp(logit - max) =================================
#define SE_BLOCKS ((V + 255) / 256)  // 197
__global__ void k7_sumexp() {
    __shared__ float sh[256];
    int i = blockIdx.x * 256 + threadIdx.x;
    float m = u2f_ord(g_max_u);
    sh[threadIdx.x] = (i < V) ? expf(g_logits[i] - m) : 0.f;
    __syncthreads();
    for (int o = 128; o; o >>= 1) {
        if (threadIdx.x < o) sh[threadIdx.x] += sh[threadIdx.x + o];
        __syncthreads();
    }
    if (!threadIdx.x) g_partial[blockIdx.x] = sh[0];
}

// ==== K8: every block redundantly reduces partials -> logZ, writes slice ====
__global__ void k8_write(float* __restrict__ out) {
    __shared__ float sh[256];
    int t = threadIdx.x;
    sh[t] = (t < SE_BLOCKS) ? g_partial[t] : 0.f;
    __syncthreads();
    for (int o = 128; o; o >>= 1) {
        if (t < o) sh[t] += sh[t + o];
        __syncthreads();
    }
    float logZ = u2f_ord(g_max_u) + logf(sh[0]);
    int i = blockIdx.x * 256 + t;
    if (i < V) out[i] = g_logits[i] - logZ;
}

// ---------------- launch ----------------------------------------------------
extern "C" void kernel_launch(void* const* d_in, const int* in_sizes, int n_in,
                              void* d_out, int out_size) {
    const int*   ids    = (const int*)d_in[0];
    const float* hidden = (const float*)d_in[1];
    const float* enc    = (const float*)d_in[2];
    const float* emb    = (const float*)d_in[3];
    const float* attn_W = (const float*)d_in[4];
    const float* attn_b = (const float*)d_in[5];
    const float* comb_W = (const float*)d_in[6];
    const float* comb_b = (const float*)d_in[7];
    const float* W_ih   = (const float*)d_in[8];
    const float* W_hh   = (const float*)d_in[9];
    const float* b_ih   = (const float*)d_in[10];
    const float* b_hh   = (const float*)d_in[11];
    const float* out_W  = (const float*)d_in[12];
    const float* out_b  = (const float*)d_in[13];
    float* out = (float*)d_out;

    k1_scores_gh<<<512, 256>>>(ids, hidden, emb, attn_W, attn_b, W_hh, b_hh);
    k2_softmax<<<1, L>>>(out);
    {
        dim3 grid(8, 4), blk(128, 8);
        k3_attn<<<grid, blk>>>(enc);
    }
    k4_x<<<256, 256>>>(ids, emb, comb_W, comb_b);
    k5_gates<<<256, 256>>>(hidden, W_ih, b_ih, out);
    k6_logits<<<(V + 7) / 8, 256>>>(out_W, out_b);
    k7_sumexp<<<SE_BLOCKS, 256>>>();
    k8_write<<<SE_BLOCKS, 256>>>(out);
}

// round 4
// speedup vs baseline: 1.3212x; 1.0714x over previous
#include <cuda_runtime.h>
#include <math.h>

#define H  1024
#define V  50257
#define L  512
#define H4 (H / 4)   // 256 float4 per H-length row

// ---------------- scratch (device globals; no allocations) ----------------
__device__ float    g_scores[L];
__device__ float    g_attn_part[8][H];
__device__ float    g_x[H];
__device__ float    g_gh[3 * H];
__device__ float    g_hnew[H];
__device__ float    g_logits[V];
__device__ unsigned g_max_u;        // order-encoded float max
__device__ float    g_partial[256]; // blockwise sum-exp partials

// ---------------- helpers ----------------
__device__ __forceinline__ float warp_reduce(float v) {
#pragma unroll
    for (int o = 16; o; o >>= 1) v += __shfl_xor_sync(0xffffffffu, v, o);
    return v;
}
__device__ __forceinline__ unsigned f2u_ord(float f) {
    int i = __float_as_int(f);
    return (i >= 0) ? ((unsigned)i | 0x80000000u) : ~((unsigned)i);
}
__device__ __forceinline__ float u2f_ord(unsigned u) {
    int i = (u & 0x80000000u) ? (int)(u & 0x7fffffffu) : ~(int)u;
    return __int_as_float(i);
}
__device__ __forceinline__ float dot4(float4 a, float4 b) {
    return a.x * b.x + a.y * b.y + a.z * b.z + a.w * b.w;
}

// ==== K1: fused  scores[l] = [emb,h0].attn_W[l]+b  AND  gh = W_hh.h0+b =====
// blocks 0..127  : scores (4 rows/block, 2 warps per 2048-row)
// blocks 128..511: gh (8 rows/block, warp per row)
__global__ void __launch_bounds__(256)
k1_scores_gh(const int* __restrict__ ids,
             const float* __restrict__ hidden,
             const float* __restrict__ emb,
             const float* __restrict__ attn_W,
             const float* __restrict__ attn_b,
             const float* __restrict__ W_hh,
             const float* __restrict__ b_hh) {
    int warp = threadIdx.x >> 5, lane = threadIdx.x & 31;
    if (blockIdx.x == 0 && threadIdx.x == 0) g_max_u = 0u;  // reset for replay
    if (blockIdx.x < 128) {
        __shared__ float s_part[8];
        int row  = blockIdx.x * 4 + (warp >> 1);
        int half = warp & 1;
        const float4* row4 = (const float4*)(attn_W + (size_t)row * 2 * H) + half * H4;
        const float4* b4   = half ? (const float4*)hidden
                                  : (const float4*)(emb + (size_t)ids[0] * H);
        float4 a[8];
#pragma unroll
        for (int k = 0; k < 8; k++) a[k] = __ldcs(row4 + lane + 32 * k);
        float4 b[8];
#pragma unroll
        for (int k = 0; k < 8; k++) b[k] = __ldg(b4 + lane + 32 * k);
        float acc = 0.f;
#pragma unroll
        for (int k = 0; k < 8; k++) acc += dot4(a[k], b[k]);
        acc = warp_reduce(acc);
        if (!lane) s_part[warp] = acc;
        __syncthreads();
        if (threadIdx.x < 4) {
            int r = blockIdx.x * 4 + threadIdx.x;
            g_scores[r] = s_part[2 * threadIdx.x] + s_part[2 * threadIdx.x + 1] + attn_b[r];
        }
    } else {
        int r = (blockIdx.x - 128) * 8 + warp;          // 0..3071
        const float4* row4 = (const float4*)(W_hh + (size_t)r * H);
        const float4* h4   = (const float4*)hidden;
        float4 a[8];
#pragma unroll
        for (int k = 0; k < 8; k++) a[k] = __ldcs(row4 + lane + 32 * k);
        float4 b[8];
#pragma unroll
        for (int k = 0; k < 8; k++) b[k] = __ldg(h4 + lane + 32 * k);
        float acc = 0.f;
#pragma unroll
        for (int k = 0; k < 8; k++) acc += dot4(a[k], b[k]);
        acc = warp_reduce(acc);
        if (!lane) g_gh[r] = acc + b_hh[r];
    }
}

// ==== K2: redundant softmax + attention-apply partials =====================
// grid (8,8) block (128,8): each block redoes the 512-softmax (cheap), then
// computes its (64-row x 128-col) partial of  attn[h] = sum_l w[l] enc[l][h]
__global__ void __launch_bounds__(1024)
k2_softmax_attn(const float* __restrict__ enc, float* __restrict__ out) {
    __shared__ float sw[L];
    __shared__ float red[L];
    __shared__ float shp[8][128];
    int t = threadIdx.y * 128 + threadIdx.x;
    float s = (t < L) ? g_scores[t] : -INFINITY;
    if (t < L) red[t] = s;
    __syncthreads();
    for (int o = L / 2; o; o >>= 1) {
        if (t < o) red[t] = fmaxf(red[t], red[t + o]);
        __syncthreads();
    }
    float m = red[0];
    __syncthreads();
    float e = (t < L) ? expf(s - m) : 0.f;
    if (t < L) red[t] = e;
    __syncthreads();
    for (int o = L / 2; o; o >>= 1) {
        if (t < o) red[t] += red[t + o];
        __syncthreads();
    }
    if (t < L) {
        float w = e / red[0];
        sw[t] = w;
        if (blockIdx.x == 0 && blockIdx.y == 0) out[V + H + t] = w;
    }
    __syncthreads();

    int col = blockIdx.x * 128 + threadIdx.x;
    int r0  = blockIdx.y * 64 + threadIdx.y * 8;
    float4 dummy;
    (void)dummy;
    float v[8];
#pragma unroll
    for (int r = 0; r < 8; r++) v[r] = __ldcs(enc + (size_t)(r0 + r) * H + col);
    float acc = 0.f;
#pragma unroll
    for (int r = 0; r < 8; r++) acc += sw[r0 + r] * v[r];
    shp[threadIdx.y][threadIdx.x] = acc;
    __syncthreads();
    if (threadIdx.y == 0) {
        float sm = 0.f;
#pragma unroll
        for (int k = 0; k < 8; k++) sm += shp[k][threadIdx.x];
        g_attn_part[blockIdx.y][col] = sm;
    }
}

// ==== K3: x = relu(comb_W.[emb, attn] + b) — staged b-operand in SMEM ======
__global__ void __launch_bounds__(256)
k3_x(const int* __restrict__ ids,
     const float* __restrict__ emb,
     const float* __restrict__ comb_W,
     const float* __restrict__ comb_b) {
    __shared__ float4 sb[2][H4];  // [0]=emb row, [1]=attn vector (8 KB)
    __shared__ float s_part[8];
    int t = threadIdx.x;
    {
        const float4* e4 = (const float4*)(emb + (size_t)ids[0] * H);
        sb[0][t] = __ldg(e4 + t);
        float4 p = *((const float4*)g_attn_part[0] + t);
#pragma unroll
        for (int k = 1; k < 8; k++) {
            float4 q = *((const float4*)g_attn_part[k] + t);
            p.x += q.x; p.y += q.y; p.z += q.z; p.w += q.w;
        }
        sb[1][t] = p;
    }
    __syncthreads();
    int warp = t >> 5, lane = t & 31;
    int row  = blockIdx.x * 4 + (warp >> 1);
    int half = warp & 1;
    const float4* row4 = (const float4*)(comb_W + (size_t)row * 2 * H) + half * H4;
    float4 a[8];
#pragma unroll
    for (int k = 0; k < 8; k++) a[k] = __ldcs(row4 + lane + 32 * k);
    float acc = 0.f;
#pragma unroll
    for (int k = 0; k < 8; k++) acc += dot4(a[k], sb[half][lane + 32 * k]);
    acc = warp_reduce(acc);
    if (!lane) s_part[warp] = acc;
    __syncthreads();
    if (t < 4) {
        int r = blockIdx.x * 4 + t;
        g_x[r] = fmaxf(s_part[2 * t] + s_part[2 * t + 1] + comb_b[r], 0.f);
    }
}

// ==== K4: gi = W_ih.x + b ; GRU gate math -> h_new =========================
// 256 blocks; warp-pair per gate-triple (half rows), x staged in SMEM
__global__ void __launch_bounds__(256)
k4_gates(const float* __restrict__ hidden,
         const float* __restrict__ W_ih,
         const float* __restrict__ b_ih,
         float* __restrict__ out) {
    __shared__ float4 sx[H4];     // 4 KB
    __shared__ float s_part[8][3];
    int t = threadIdx.x;
    sx[t] = *((const float4*)g_x + t);
    __syncthreads();
    int warp = t >> 5, lane = t & 31;
    int i    = blockIdx.x * 4 + (warp >> 1);   // 0..1023
    int half = warp & 1;
    int base = half * (H4 / 2);
    const float4* r0 = (const float4*)(W_ih + (size_t)i * H)           + base;
    const float4* r1 = (const float4*)(W_ih + (size_t)(H + i) * H)     + base;
    const float4* r2 = (const float4*)(W_ih + (size_t)(2 * H + i) * H) + base;
    float4 a0[4], a1[4], a2[4];
#pragma unroll
    for (int k = 0; k < 4; k++) a0[k] = __ldcs(r0 + lane + 32 * k);
#pragma unroll
    for (int k = 0; k < 4; k++) a1[k] = __ldcs(r1 + lane + 32 * k);
#pragma unroll
    for (int k = 0; k < 4; k++) a2[k] = __ldcs(r2 + lane + 32 * k);
    float c0 = 0.f, c1 = 0.f, c2 = 0.f;
#pragma unroll
    for (int k = 0; k < 4; k++) {
        float4 b = sx[base + lane + 32 * k];
        c0 += dot4(a0[k], b);
        c1 += dot4(a1[k], b);
        c2 += dot4(a2[k], b);
    }
    c0 = warp_reduce(c0);
    c1 = warp_reduce(c1);
    c2 = warp_reduce(c2);
    if (!lane) { s_part[warp][0] = c0; s_part[warp][1] = c1; s_part[warp][2] = c2; }
    __syncthreads();
    if (t < 4) {
        int gi_i = blockIdx.x * 4 + t;
        float ir  = s_part[2 * t][0] + s_part[2 * t + 1][0] + b_ih[gi_i];
        float iz  = s_part[2 * t][1] + s_part[2 * t + 1][1] + b_ih[H + gi_i];
        float in_ = s_part[2 * t][2] + s_part[2 * t + 1][2] + b_ih[2 * H + gi_i];
        float hr = g_gh[gi_i], hz = g_gh[H + gi_i], hn = g_gh[2 * H + gi_i];
        float r = 1.f / (1.f + expf(-(ir + hr)));
        float z = 1.f / (1.f + expf(-(iz + hz)));
        float n = tanhf(in_ + r * hn);
        float h0 = hidden[gi_i];
        float hnew = (1.f - z) * n + z * h0;
        g_hnew[gi_i] = hnew;
        out[V + gi_i] = hnew;
    }
}

// ==== K5: vocab GEMV (h staged in SMEM) + deterministic global max =========
__global__ void __launch_bounds__(256)
k5_logits(const float* __restrict__ out_W,
          const float* __restrict__ out_b) {
    __shared__ float4 sh4[H4];    // 4 KB
    __shared__ float smax[8];
    int t = threadIdx.x;
    sh4[t] = *((const float4*)g_hnew + t);
    __syncthreads();
    int warp = t >> 5, lane = t & 31;
    int r = blockIdx.x * 8 + warp;
    float logit = -INFINITY;
    if (r < V) {
        const float4* row4 = (const float4*)(out_W + (size_t)r * H);
        float4 a[8];
#pragma unroll
        for (int k = 0; k < 8; k++) a[k] = __ldcs(row4 + lane + 32 * k);
        float acc = 0.f;
#pragma unroll
        for (int k = 0; k < 8; k++) acc += dot4(a[k], sh4[lane + 32 * k]);
        acc = warp_reduce(acc);
        logit = acc + out_b[r];
        if (!lane) g_logits[r] = logit;
    }
    if (!lane) smax[warp] = logit;
    __syncthreads();
    if (t == 0) {
        float m = smax[0];
#pragma unroll
        for (int k = 1; k < 8; k++) m = fmaxf(m, smax[k]);
        atomicMax(&g_max_u, f2u_ord(m));   // order-invariant -> deterministic
    }
}

// ==== K6: blockwise sum of exp(logit - max) ================================
#define SE_BLOCKS ((V + 255) / 256)  // 197
__global__ void k6_sumexp() {
    __shared__ float sh[256];
    int i = blockIdx.x * 256 + threadIdx.x;
    float m = u2f_ord(g_max_u);
    sh[threadIdx.x] = (i < V) ? expf(g_logits[i] - m) : 0.f;
    __syncthreads();
    for (int o = 128; o; o >>= 1) {
        if (threadIdx.x < o) sh[threadIdx.x] += sh[threadIdx.x + o];
        __syncthreads();
    }
    if (!threadIdx.x) g_partial[blockIdx.x] = sh[0];
}

// ==== K7: every block redundantly reduces partials -> logZ, writes slice ===
__global__ void k7_write(float* __restrict__ out) {
    __shared__ float sh[256];
    int t = threadIdx.x;
    sh[t] = (t < SE_BLOCKS) ? g_partial[t] : 0.f;
    __syncthreads();
    for (int o = 128; o; o >>= 1) {
        if (t < o) sh[t] += sh[t + o];
        __syncthreads();
    }
    float logZ = u2f_ord(g_max_u) + logf(sh[0]);
    int i = blockIdx.x * 256 + t;
    if (i < V) out[i] = g_logits[i] - logZ;
}

// ---------------- launch ----------------------------------------------------
extern "C" void kernel_launch(void* const* d_in, const int* in_sizes, int n_in,
                              void* d_out, int out_size) {
    const int*   ids    = (const int*)d_in[0];
    const float* hidden = (const float*)d_in[1];
    const float* enc    = (const float*)d_in[2];
    const float* emb    = (const float*)d_in[3];
    const float* attn_W = (const float*)d_in[4];
    const float* attn_b = (const float*)d_in[5];
    const float* comb_W = (const float*)d_in[6];
    const float* comb_b = (const float*)d_in[7];
    const float* W_ih   = (const float*)d_in[8];
    const float* W_hh   = (const float*)d_in[9];
    const float* b_ih   = (const float*)d_in[10];
    const float* b_hh   = (const float*)d_in[11];
    const float* out_W  = (const float*)d_in[12];
    const float* out_b  = (const float*)d_in[13];
    float* out = (float*)d_out;

    k1_scores_gh<<<512, 256>>>(ids, hidden, emb, attn_W, attn_b, W_hh, b_hh);
    {
        dim3 grid(8, 8), blk(128, 8);
        k2_softmax_attn<<<grid, blk>>>(enc, out);
    }
    k3_x<<<256, 256>>>(ids, emb, comb_W, comb_b);
    k4_gates<<<256, 256>>>(hidden, W_ih, b_ih, out);
    k5_logits<<<(V + 7) / 8, 256>>>(out_W, out_b);
    k6_sumexp<<<SE_BLOCKS, 256>>>();
    k7_write<<<SE_BLOCKS, 256>>>(out);
}